// round 13
// baseline (speedup 1.0000x reference)
#include <cuda_runtime.h>
#include <cstdint>

// YOLO-v1 loss, fused single-pass reduction.
// R12 (re-run after infra failure): R10's warp-parallel cp.async 3-stage
// pipeline, with
//  (a) prefetch issued BEFORE compute (2 tiles in flight during compute), and
//  (b) single-kernel finalization (no zero_kernel launch): per-block partials
//      in device global memory, last block reduces and writes the scalar.

static constexpr int CH   = 30;   // C + 5*B
static constexpr int TILE = 128;  // cells per pipeline stage
static constexpr int TPB  = 256;  // threads per block
static constexpr int STAGE_FLOATS = TILE * CH;   // 3840 floats per tensor-stage
static constexpr int NSTAGE = 3;
static constexpr int GRID = 304;  // 152 SMs * 2 resident CTAs (92KB smem each)

__device__ float g_partials[GRID];
__device__ int   g_ticket = 0;

__device__ __forceinline__ void cp16(float4* smem, const float4* gmem) {
    uint32_t s = (uint32_t)__cvta_generic_to_shared(smem);
    asm volatile("cp.async.cg.shared.global [%0], [%1], 16;\n" :: "r"(s), "l"(gmem));
}
__device__ __forceinline__ void cp_commit() {
    asm volatile("cp.async.commit_group;\n" ::: "memory");
}
__device__ __forceinline__ void cp_wait1() {   // block until <=1 group pending
    asm volatile("cp.async.wait_group 1;\n" ::: "memory");
}

__device__ __forceinline__ float iou_f(
    float ax, float ay, float aw, float ah,
    float bx, float by, float bw, float bh)
{
    float ax1 = ax - aw * 0.5f, ay1 = ay - ah * 0.5f;
    float ax2 = ax + aw * 0.5f, ay2 = ay + ah * 0.5f;
    float bx1 = bx - bw * 0.5f, by1 = by - bh * 0.5f;
    float bx2 = bx + bw * 0.5f, by2 = by + bh * 0.5f;
    float x1 = fmaxf(ax1, bx1), y1 = fmaxf(ay1, by1);
    float x2 = fminf(ax2, bx2), y2 = fminf(ay2, by2);
    float inter = fmaxf(x2 - x1, 0.0f) * fmaxf(y2 - y1, 0.0f);
    float aa = fabsf((ax2 - ax1) * (ay2 - ay1));
    float ab = fabsf((bx2 - bx1) * (by2 - by1));
    return inter / (aa + ab - inter + 1e-6f);
}

extern __shared__ float smem_dyn[];  // [NSTAGE][2 tensors][STAGE_FLOATS]

__device__ __forceinline__ void prefetch_tile(
    const float* __restrict__ pred, const float* __restrict__ targ,
    float* pbuf, float* tbuf, long tile, int ncells)
{
    long cbase = tile * TILE;
    int  cells = ncells - (int)cbase;
    if (cells > TILE) cells = TILE;
    int nfl = cells * CH;
    const float* pg = pred + cbase * CH;
    const float* tg = targ + cbase * CH;

    int nf4 = nfl >> 2;
    const float4* pg4 = reinterpret_cast<const float4*>(pg);
    const float4* tg4 = reinterpret_cast<const float4*>(tg);
    float4* pb4 = reinterpret_cast<float4*>(pbuf);
    float4* tb4 = reinterpret_cast<float4*>(tbuf);
    for (int q = threadIdx.x; q < nf4; q += TPB) {
        cp16(&pb4[q], &pg4[q]);
        cp16(&tb4[q], &tg4[q]);
    }
    for (int f = (nf4 << 2) + threadIdx.x; f < nfl; f += TPB) {  // odd tail
        pbuf[f] = pg[f];
        tbuf[f] = tg[f];
    }
}

__device__ __forceinline__ float compute_tile(
    const float* __restrict__ pbuf, const float* __restrict__ tbuf,
    long tile, int ncells)
{
    long cbase = tile * TILE;
    int  cells = ncells - (int)cbase;
    if (cells > TILE) cells = TILE;
    if ((int)threadIdx.x >= cells) return 0.0f;

    const float* p = pbuf + threadIdx.x * CH;
    const float* t = tbuf + threadIdx.x * CH;

    float t20 = t[20];
    float t21 = t[21], t22 = t[22], t23 = t[23], t24 = t[24];
    float iou1 = iou_f(p[21], p[22], p[23], p[24], t21, t22, t23, t24);
    float iou2 = iou_f(p[26], p[27], p[28], p[29], t21, t22, t23, t24);

    // bestbox selects p[29] (as written in the reference) else p[20]
    float pc = (iou2 > iou1) ? p[29] : p[20];
    float e  = t20;
    float no = 1.0f - e;

    float d = e * pc - e * t20;          // obj loss
    float acc = d * d;

    d = no * p[20] - no * t20; float nl = d * d;   // noobj (x0.5)
    d = no * p[29] - no * t20; nl += d * d;
    acc += 0.5f * nl;

    float cl = 0.0f;                      // class loss
    #pragma unroll
    for (int k = 0; k < 20; k++) {
        float dd = e * p[k] - e * t[k];
        cl += dd * dd;
    }
    acc += cl;
    // box_loss == 0 in the reference; LAMBDA_COORD term drops out.
    return acc;
}

__global__ __launch_bounds__(TPB) void yolo_loss_kernel(
    const float* __restrict__ pred, const float* __restrict__ targ,
    float* __restrict__ out, int ncells, int ntiles)
{
    float* pb[NSTAGE];
    float* tb[NSTAGE];
    #pragma unroll
    for (int s = 0; s < NSTAGE; s++) {
        pb[s] = smem_dyn + (2 * s)     * STAGE_FLOATS;
        tb[s] = smem_dyn + (2 * s + 1) * STAGE_FLOATS;
    }

    float acc = 0.0f;

    // Prologue: prefetch tiles t0, t1 into stages 0, 1.
    long t0 = blockIdx.x;
    long t1 = t0 + gridDim.x;
    if (t0 < ntiles) prefetch_tile(pred, targ, pb[0], tb[0], t0, ncells);
    cp_commit();
    if (t1 < ntiles) prefetch_tile(pred, targ, pb[1], tb[1], t1, ncells);
    cp_commit();

    int it = 0;
    for (long tile = t0; tile < ntiles; tile += gridDim.x, it++) {
        cp_wait1();          // oldest pending group (this tile) complete
        __syncthreads();     // copies visible to all; orders stage reuse below

        // Prefetch FIRST: stage (it+2)%3 was last read at iter it-1, which
        // happens-before the sync above. Issuing now keeps 2 tiles in flight
        // through the whole compute phase.
        long nxt = tile + 2L * gridDim.x;
        int  ns  = (it + 2) % NSTAGE;
        if (nxt < ntiles)
            prefetch_tile(pred, targ, pb[ns], tb[ns], nxt, ncells);
        cp_commit();         // commit even if empty: fixed group accounting

        int s = it % NSTAGE;
        acc += compute_tile(pb[s], tb[s], tile, ncells);
    }

    // Block reduction: warp shuffle -> smem -> thread 0.
    #pragma unroll
    for (int off = 16; off; off >>= 1)
        acc += __shfl_down_sync(0xffffffffu, acc, off);

    __shared__ float wsum[TPB / 32];
    __shared__ int   is_last;
    int wid = threadIdx.x >> 5, lid = threadIdx.x & 31;
    if (lid == 0) wsum[wid] = acc;
    __syncthreads();
    if (threadIdx.x == 0) {
        float v = 0.0f;
        #pragma unroll
        for (int w = 0; w < TPB / 32; w++) v += wsum[w];
        g_partials[blockIdx.x] = v;
        __threadfence();
        int old = atomicAdd(&g_ticket, 1);
        is_last = (old == (int)gridDim.x - 1);
    }
    __syncthreads();

    if (is_last) {
        // Last block: reduce all partials, write scalar, reset ticket.
        int nb = (int)gridDim.x;
        float v = 0.0f;
        for (int i = threadIdx.x; i < nb; i += TPB)
            v += g_partials[i];
        #pragma unroll
        for (int off = 16; off; off >>= 1)
            v += __shfl_down_sync(0xffffffffu, v, off);
        if (lid == 0) wsum[wid] = v;
        __syncthreads();
        if (threadIdx.x == 0) {
            float tot = 0.0f;
            #pragma unroll
            for (int w = 0; w < TPB / 32; w++) tot += wsum[w];
            out[0] = tot;
            g_ticket = 0;   // restore for next launch / graph replay
        }
    }
}

extern "C" void kernel_launch(void* const* d_in, const int* in_sizes, int n_in,
                              void* d_out, int out_size)
{
    const float* pred = (const float*)d_in[0];
    const float* targ = (const float*)d_in[1];
    float* out = (float*)d_out;

    int ncells = in_sizes[0] / CH;
    int ntiles = (ncells + TILE - 1) / TILE;
    size_t shmem = (size_t)(2 * NSTAGE * STAGE_FLOATS) * sizeof(float); // 92160 B

    cudaFuncSetAttribute(yolo_loss_kernel,
                         cudaFuncAttributeMaxDynamicSharedMemorySize, (int)shmem);

    int nblocks = GRID < ntiles ? GRID : ntiles;
    yolo_loss_kernel<<<nblocks, TPB, shmem>>>(pred, targ, out, ncells, ntiles);
}

// round 15
// speedup vs baseline: 1.1377x; 1.1377x over previous
#include <cuda_runtime.h>
#include <cstdint>

// YOLO-v1 loss, fused single-pass reduction.
// R14: EXACT R10 pipeline order (wait -> sync -> compute -> prefetch -> commit;
// the proven-fast schedule), plus single-kernel finalization only:
// per-block partials in device globals, ticket atomic, last block reduces
// and writes the scalar (removes the zero_kernel launch).

static constexpr int CH   = 30;   // C + 5*B
static constexpr int TILE = 128;  // cells per pipeline stage
static constexpr int TPB  = 256;  // threads per block
static constexpr int STAGE_FLOATS = TILE * CH;   // 3840 floats per tensor-stage
static constexpr int NSTAGE = 3;
static constexpr int GRID = 304;  // 152 SMs * 2 resident CTAs (92KB smem each)

__device__ float g_partials[GRID];
__device__ int   g_ticket = 0;

__device__ __forceinline__ void cp16(float4* smem, const float4* gmem) {
    uint32_t s = (uint32_t)__cvta_generic_to_shared(smem);
    asm volatile("cp.async.cg.shared.global [%0], [%1], 16;\n" :: "r"(s), "l"(gmem));
}
__device__ __forceinline__ void cp_commit() {
    asm volatile("cp.async.commit_group;\n" ::: "memory");
}
__device__ __forceinline__ void cp_wait1() {   // block until <=1 group pending
    asm volatile("cp.async.wait_group 1;\n" ::: "memory");
}

__device__ __forceinline__ float iou_f(
    float ax, float ay, float aw, float ah,
    float bx, float by, float bw, float bh)
{
    float ax1 = ax - aw * 0.5f, ay1 = ay - ah * 0.5f;
    float ax2 = ax + aw * 0.5f, ay2 = ay + ah * 0.5f;
    float bx1 = bx - bw * 0.5f, by1 = by - bh * 0.5f;
    float bx2 = bx + bw * 0.5f, by2 = by + bh * 0.5f;
    float x1 = fmaxf(ax1, bx1), y1 = fmaxf(ay1, by1);
    float x2 = fminf(ax2, bx2), y2 = fminf(ay2, by2);
    float inter = fmaxf(x2 - x1, 0.0f) * fmaxf(y2 - y1, 0.0f);
    float aa = fabsf((ax2 - ax1) * (ay2 - ay1));
    float ab = fabsf((bx2 - bx1) * (by2 - by1));
    return inter / (aa + ab - inter + 1e-6f);
}

extern __shared__ float smem_dyn[];  // [NSTAGE][2 tensors][STAGE_FLOATS]

__device__ __forceinline__ void prefetch_tile(
    const float* __restrict__ pred, const float* __restrict__ targ,
    float* pbuf, float* tbuf, long tile, int ncells)
{
    long cbase = tile * TILE;
    int  cells = ncells - (int)cbase;
    if (cells > TILE) cells = TILE;
    int nfl = cells * CH;
    const float* pg = pred + cbase * CH;
    const float* tg = targ + cbase * CH;

    int nf4 = nfl >> 2;
    const float4* pg4 = reinterpret_cast<const float4*>(pg);
    const float4* tg4 = reinterpret_cast<const float4*>(tg);
    float4* pb4 = reinterpret_cast<float4*>(pbuf);
    float4* tb4 = reinterpret_cast<float4*>(tbuf);
    for (int q = threadIdx.x; q < nf4; q += TPB) {
        cp16(&pb4[q], &pg4[q]);
        cp16(&tb4[q], &tg4[q]);
    }
    for (int f = (nf4 << 2) + threadIdx.x; f < nfl; f += TPB) {  // odd tail
        pbuf[f] = pg[f];
        tbuf[f] = tg[f];
    }
}

__device__ __forceinline__ float compute_tile(
    const float* __restrict__ pbuf, const float* __restrict__ tbuf,
    long tile, int ncells)
{
    long cbase = tile * TILE;
    int  cells = ncells - (int)cbase;
    if (cells > TILE) cells = TILE;
    if ((int)threadIdx.x >= cells) return 0.0f;

    const float* p = pbuf + threadIdx.x * CH;
    const float* t = tbuf + threadIdx.x * CH;

    float t20 = t[20];
    float t21 = t[21], t22 = t[22], t23 = t[23], t24 = t[24];
    float iou1 = iou_f(p[21], p[22], p[23], p[24], t21, t22, t23, t24);
    float iou2 = iou_f(p[26], p[27], p[28], p[29], t21, t22, t23, t24);

    // bestbox selects p[29] (as written in the reference) else p[20]
    float pc = (iou2 > iou1) ? p[29] : p[20];
    float e  = t20;
    float no = 1.0f - e;

    float d = e * pc - e * t20;          // obj loss
    float acc = d * d;

    d = no * p[20] - no * t20; float nl = d * d;   // noobj (x0.5)
    d = no * p[29] - no * t20; nl += d * d;
    acc += 0.5f * nl;

    float cl = 0.0f;                      // class loss
    #pragma unroll
    for (int k = 0; k < 20; k++) {
        float dd = e * p[k] - e * t[k];
        cl += dd * dd;
    }
    acc += cl;
    // box_loss == 0 in the reference; LAMBDA_COORD term drops out.
    return acc;
}

__global__ __launch_bounds__(TPB) void yolo_loss_kernel(
    const float* __restrict__ pred, const float* __restrict__ targ,
    float* __restrict__ out, int ncells, int ntiles)
{
    float* pb[NSTAGE];
    float* tb[NSTAGE];
    #pragma unroll
    for (int s = 0; s < NSTAGE; s++) {
        pb[s] = smem_dyn + (2 * s)     * STAGE_FLOATS;
        tb[s] = smem_dyn + (2 * s + 1) * STAGE_FLOATS;
    }

    float acc = 0.0f;

    // Prologue: prefetch tiles t0, t1 into stages 0, 1.
    long t0 = blockIdx.x;
    long t1 = t0 + gridDim.x;
    if (t0 < ntiles) prefetch_tile(pred, targ, pb[0], tb[0], t0, ncells);
    cp_commit();
    if (t1 < ntiles) prefetch_tile(pred, targ, pb[1], tb[1], t1, ncells);
    cp_commit();

    int it = 0;
    for (long tile = t0; tile < ntiles; tile += gridDim.x, it++) {
        cp_wait1();          // oldest pending group (this tile) complete
        __syncthreads();     // all threads' copies visible; also orders reuse

        int s = it % NSTAGE;
        acc += compute_tile(pb[s], tb[s], tile, ncells);

        long nxt = tile + 2L * gridDim.x;
        int  ns  = (it + 2) % NSTAGE;   // last read at iter it-1; ordered by
                                        // the sync at this iter's top.
        if (nxt < ntiles)
            prefetch_tile(pred, targ, pb[ns], tb[ns], nxt, ncells);
        cp_commit();         // commit even if empty: fixed group accounting
    }

    // Block reduction: warp shuffle -> smem -> thread 0.
    #pragma unroll
    for (int off = 16; off; off >>= 1)
        acc += __shfl_down_sync(0xffffffffu, acc, off);

    __shared__ float wsum[TPB / 32];
    __shared__ int   is_last;
    int wid = threadIdx.x >> 5, lid = threadIdx.x & 31;
    if (lid == 0) wsum[wid] = acc;
    __syncthreads();
    if (threadIdx.x == 0) {
        float v = 0.0f;
        #pragma unroll
        for (int w = 0; w < TPB / 32; w++) v += wsum[w];
        g_partials[blockIdx.x] = v;
        __threadfence();
        int old = atomicAdd(&g_ticket, 1);
        is_last = (old == (int)gridDim.x - 1);
    }
    __syncthreads();

    if (is_last) {
        // Last block: reduce all partials, write scalar, reset ticket.
        int nb = (int)gridDim.x;
        float v = 0.0f;
        for (int i = threadIdx.x; i < nb; i += TPB)
            v += g_partials[i];
        #pragma unroll
        for (int off = 16; off; off >>= 1)
            v += __shfl_down_sync(0xffffffffu, v, off);
        if (lid == 0) wsum[wid] = v;
        __syncthreads();
        if (threadIdx.x == 0) {
            float tot = 0.0f;
            #pragma unroll
            for (int w = 0; w < TPB / 32; w++) tot += wsum[w];
            out[0] = tot;
            g_ticket = 0;   // restore for next launch / graph replay
        }
    }
}

extern "C" void kernel_launch(void* const* d_in, const int* in_sizes, int n_in,
                              void* d_out, int out_size)
{
    const float* pred = (const float*)d_in[0];
    const float* targ = (const float*)d_in[1];
    float* out = (float*)d_out;

    int ncells = in_sizes[0] / CH;
    int ntiles = (ncells + TILE - 1) / TILE;
    size_t shmem = (size_t)(2 * NSTAGE * STAGE_FLOATS) * sizeof(float); // 92160 B

    cudaFuncSetAttribute(yolo_loss_kernel,
                         cudaFuncAttributeMaxDynamicSharedMemorySize, (int)shmem);

    int nblocks = GRID < ntiles ? GRID : ntiles;
    yolo_loss_kernel<<<nblocks, TPB, shmem>>>(pred, targ, out, ncells, ntiles);
}

// round 16
// speedup vs baseline: 1.2671x; 1.1138x over previous
#include <cuda_runtime.h>
#include <cstdint>

// YOLO-v1 loss, fused single-pass reduction.
// RE-BASELINE: exact R10 kernel (best measured: 121.0 us, DRAM 84%).
// Persistent CTAs + cp.async 3-stage pipeline, ONE barrier per tile.
// Order per iter: wait(oldest) -> sync -> compute(t_i) -> prefetch(t_{i+2}).

static constexpr int CH   = 30;   // C + 5*B
static constexpr int TILE = 128;  // cells per pipeline stage
static constexpr int TPB  = 256;  // threads per block
static constexpr int STAGE_FLOATS = TILE * CH;   // 3840 floats per tensor-stage
static constexpr int NSTAGE = 3;
static constexpr int GRID = 304;  // 152 SMs * 2 resident CTAs (92KB smem each)

__global__ void zero_kernel(float* out) { out[0] = 0.0f; }

__device__ __forceinline__ void cp16(float4* smem, const float4* gmem) {
    uint32_t s = (uint32_t)__cvta_generic_to_shared(smem);
    asm volatile("cp.async.cg.shared.global [%0], [%1], 16;\n" :: "r"(s), "l"(gmem));
}
__device__ __forceinline__ void cp_commit() {
    asm volatile("cp.async.commit_group;\n" ::: "memory");
}
__device__ __forceinline__ void cp_wait1() {   // block until <=1 group pending
    asm volatile("cp.async.wait_group 1;\n" ::: "memory");
}

__device__ __forceinline__ float iou_f(
    float ax, float ay, float aw, float ah,
    float bx, float by, float bw, float bh)
{
    float ax1 = ax - aw * 0.5f, ay1 = ay - ah * 0.5f;
    float ax2 = ax + aw * 0.5f, ay2 = ay + ah * 0.5f;
    float bx1 = bx - bw * 0.5f, by1 = by - bh * 0.5f;
    float bx2 = bx + bw * 0.5f, by2 = by + bh * 0.5f;
    float x1 = fmaxf(ax1, bx1), y1 = fmaxf(ay1, by1);
    float x2 = fminf(ax2, bx2), y2 = fminf(ay2, by2);
    float inter = fmaxf(x2 - x1, 0.0f) * fmaxf(y2 - y1, 0.0f);
    float aa = fabsf((ax2 - ax1) * (ay2 - ay1));
    float ab = fabsf((bx2 - bx1) * (by2 - by1));
    return inter / (aa + ab - inter + 1e-6f);
}

extern __shared__ float smem_dyn[];  // [NSTAGE][2 tensors][STAGE_FLOATS]

__device__ __forceinline__ void prefetch_tile(
    const float* __restrict__ pred, const float* __restrict__ targ,
    float* pbuf, float* tbuf, long tile, int ncells)
{
    long cbase = tile * TILE;
    int  cells = ncells - (int)cbase;
    if (cells > TILE) cells = TILE;
    int nfl = cells * CH;
    const float* pg = pred + cbase * CH;
    const float* tg = targ + cbase * CH;

    int nf4 = nfl >> 2;
    const float4* pg4 = reinterpret_cast<const float4*>(pg);
    const float4* tg4 = reinterpret_cast<const float4*>(tg);
    float4* pb4 = reinterpret_cast<float4*>(pbuf);
    float4* tb4 = reinterpret_cast<float4*>(tbuf);
    for (int q = threadIdx.x; q < nf4; q += TPB) {
        cp16(&pb4[q], &pg4[q]);
        cp16(&tb4[q], &tg4[q]);
    }
    for (int f = (nf4 << 2) + threadIdx.x; f < nfl; f += TPB) {  // odd tail
        pbuf[f] = pg[f];
        tbuf[f] = tg[f];
    }
}

__device__ __forceinline__ float compute_tile(
    const float* __restrict__ pbuf, const float* __restrict__ tbuf,
    long tile, int ncells)
{
    long cbase = tile * TILE;
    int  cells = ncells - (int)cbase;
    if (cells > TILE) cells = TILE;
    if ((int)threadIdx.x >= cells) return 0.0f;

    const float* p = pbuf + threadIdx.x * CH;
    const float* t = tbuf + threadIdx.x * CH;

    float t20 = t[20];
    float t21 = t[21], t22 = t[22], t23 = t[23], t24 = t[24];
    float iou1 = iou_f(p[21], p[22], p[23], p[24], t21, t22, t23, t24);
    float iou2 = iou_f(p[26], p[27], p[28], p[29], t21, t22, t23, t24);

    // bestbox selects p[29] (as written in the reference) else p[20]
    float pc = (iou2 > iou1) ? p[29] : p[20];
    float e  = t20;
    float no = 1.0f - e;

    float d = e * pc - e * t20;          // obj loss
    float acc = d * d;

    d = no * p[20] - no * t20; float nl = d * d;   // noobj (x0.5)
    d = no * p[29] - no * t20; nl += d * d;
    acc += 0.5f * nl;

    float cl = 0.0f;                      // class loss
    #pragma unroll
    for (int k = 0; k < 20; k++) {
        float dd = e * p[k] - e * t[k];
        cl += dd * dd;
    }
    acc += cl;
    // box_loss == 0 in the reference; LAMBDA_COORD term drops out.
    return acc;
}

__global__ __launch_bounds__(TPB) void yolo_loss_kernel(
    const float* __restrict__ pred, const float* __restrict__ targ,
    float* __restrict__ out, int ncells, int ntiles)
{
    float* pb[NSTAGE];
    float* tb[NSTAGE];
    #pragma unroll
    for (int s = 0; s < NSTAGE; s++) {
        pb[s] = smem_dyn + (2 * s)     * STAGE_FLOATS;
        tb[s] = smem_dyn + (2 * s + 1) * STAGE_FLOATS;
    }

    float acc = 0.0f;

    // Prologue: prefetch tiles t0, t1 into stages 0, 1.
    long t0 = blockIdx.x;
    long t1 = t0 + gridDim.x;
    if (t0 < ntiles) prefetch_tile(pred, targ, pb[0], tb[0], t0, ncells);
    cp_commit();
    if (t1 < ntiles) prefetch_tile(pred, targ, pb[1], tb[1], t1, ncells);
    cp_commit();

    int it = 0;
    for (long tile = t0; tile < ntiles; tile += gridDim.x, it++) {
        cp_wait1();          // oldest pending group (this tile) complete
        __syncthreads();     // all threads' copies visible; also orders reuse

        int s = it % NSTAGE;
        acc += compute_tile(pb[s], tb[s], tile, ncells);

        long nxt = tile + 2L * gridDim.x;
        int  ns  = (it + 2) % NSTAGE;
        if (nxt < ntiles)
            prefetch_tile(pred, targ, pb[ns], tb[ns], nxt, ncells);
        cp_commit();         // commit even if empty: keeps group accounting fixed
    }

    // final reduction: warp shuffle -> block -> one atomic per block
    #pragma unroll
    for (int off = 16; off; off >>= 1)
        acc += __shfl_down_sync(0xffffffffu, acc, off);

    __shared__ float wsum[TPB / 32];
    int wid = threadIdx.x >> 5, lid = threadIdx.x & 31;
    if (lid == 0) wsum[wid] = acc;
    __syncthreads();
    if (wid == 0) {
        float v = (lid < TPB / 32) ? wsum[lid] : 0.0f;
        #pragma unroll
        for (int off = 4; off; off >>= 1)
            v += __shfl_down_sync(0xffffffffu, v, off);
        if (lid == 0) atomicAdd(out, v);
    }
}

extern "C" void kernel_launch(void* const* d_in, const int* in_sizes, int n_in,
                              void* d_out, int out_size)
{
    const float* pred = (const float*)d_in[0];
    const float* targ = (const float*)d_in[1];
    float* out = (float*)d_out;

    int ncells = in_sizes[0] / CH;
    int ntiles = (ncells + TILE - 1) / TILE;
    size_t shmem = (size_t)(2 * NSTAGE * STAGE_FLOATS) * sizeof(float); // 92160 B

    cudaFuncSetAttribute(yolo_loss_kernel,
                         cudaFuncAttributeMaxDynamicSharedMemorySize, (int)shmem);

    int nblocks = GRID < ntiles ? GRID : ntiles;
    zero_kernel<<<1, 1>>>(out);
    yolo_loss_kernel<<<nblocks, TPB, shmem>>>(pred, targ, out, ncells, ntiles);
}